// round 15
// baseline (speedup 1.0000x reference)
#include <cuda_runtime.h>
#include <math.h>

#define T_TOK   2048
#define H_DIM   128
#define H4_DIM  512
#define N_NODES 256
#define TB      8    // tokens per chunk
#define NC      4    // token chunks in grid (covers 32 tokens; stride loop beyond)

// Scratch (allocation-free per harness rules)
__device__ int   g_count[N_NODES];
__device__ int   g_tokens[N_NODES * T_TOK];
__device__ float g_h[T_TOK * H4_DIM];   // 4 MB intermediate (L2-resident)

// Single-launch prep: 1024 threads, smem counters, 2 tokens/thread.
__global__ void prep_kernel(const int* __restrict__ node_ind) {
    __shared__ int scnt[N_NODES];
    const int tid = threadIdx.x;
    if (tid < N_NODES) scnt[tid] = 0;
    __syncthreads();
    #pragma unroll
    for (int t = tid; t < T_TOK; t += 1024) {
        int n = node_ind[t];
        int pos = atomicAdd(&scnt[n], 1);
        g_tokens[n * T_TOK + pos] = t;
    }
    __syncthreads();
    if (tid < N_NODES) g_count[tid] = scnt[tid];
}

__device__ __forceinline__ float gelu_exact(float v) {
    return 0.5f * v * (1.0f + erff(v * 0.70710678118654752f));
}

// ============================================================================
// Layer 1: grid = N_NODES*NC. CTA (n, tc) processes ALL 16 row-items (32 rows
// each) of node n for its token chunk. 128 thr / 4 warps. Warp w owns rows
// q*32 + w*8 + it*4 + g. lane=(g<<3)|c; xs float4 [j*8+c]: 1 wavefront.
// ROLLING QUARTER PREFETCH: after compute phase j, wv[*][j] is overwritten
// with next item's quarter-j weights -> continuous DRAM stream, no extra regs.
// ============================================================================
__global__ __launch_bounds__(128, 4)
void layer1_kernel(const float* __restrict__ x,
                   const float* __restrict__ W1,
                   const float* __restrict__ b1) {
    __shared__ float xs[TB][H_DIM];   // 4 KB
    __shared__ int   stoks[TB];

    const int bid = blockIdx.x;
    const int tc  = bid & (NC - 1);
    const int n   = bid >> 2;
    const int base0 = tc * TB;

    const int tid = threadIdx.x;

    // Speculative token-id load (independent of count; address always valid)
    int spec_tok = 0;
    if (tid < TB) spec_tok = g_tokens[n * T_TOK + base0 + tid];
    const int nt_total = g_count[n];
    if (base0 >= nt_total) return;

    const int w    = tid >> 5;
    const int lane = tid & 31;
    const int g    = lane >> 3;   // row slot 0..3 (broadcast group)
    const int c    = lane & 7;    // k-chunk 0..7
    const int rbase = w * 8 + g;  // row within item = rbase + it*4

    const float* W1n = W1 + (size_t)n * H4_DIM * H_DIM;
    const float* b1n = b1 + n * H4_DIM;

    // Initial weights + biases for item 0
    float4 wv[2][4];
    float  bias[2];
    #pragma unroll
    for (int it = 0; it < 2; it++) {
        const float4* wr = (const float4*)(W1n + (size_t)(rbase + it * 4) * H_DIM);
        #pragma unroll
        for (int j = 0; j < 4; j++) wv[it][j] = wr[j * 8 + c];
        bias[it] = b1n[rbase + it * 4];
    }

    for (int base = base0; base < nt_total; base += NC * TB) {
        const int nt = min(TB, nt_total - base);

        __syncthreads();
        if (tid < nt)
            stoks[tid] = (base == base0) ? spec_tok
                                         : g_tokens[n * T_TOK + base + tid];
        __syncthreads();
        #pragma unroll
        for (int k = 0; k < 2; k++) {
            int idx = tid + k * 128;
            int tk = idx >> 5;
            int l4 = idx & 31;
            if (tk < nt)
                ((float4*)xs[tk])[l4] =
                    ((const float4*)(x + (size_t)stoks[tk] * H_DIM))[l4];
        }
        __syncthreads();

        #pragma unroll 1
        for (int q = 0; q < 16; q++) {
            const int qn = (q + 1) & 15;   // wrap -> regs hold item 0 after last
            float bias_nxt[2];

            float acc[2][TB];
            #pragma unroll
            for (int it = 0; it < 2; it++)
                #pragma unroll
                for (int t = 0; t < TB; t++) acc[it][t] = 0.f;

            #pragma unroll
            for (int j = 0; j < 4; j++) {
                #pragma unroll
                for (int t = 0; t < TB; t++) {
                    if (t < nt) {
                        float4 xv = ((const float4*)xs[t])[j * 8 + c];
                        acc[0][t] += wv[0][j].x * xv.x + wv[0][j].y * xv.y
                                   + wv[0][j].z * xv.z + wv[0][j].w * xv.w;
                        acc[1][t] += wv[1][j].x * xv.x + wv[1][j].y * xv.y
                                   + wv[1][j].z * xv.z + wv[1][j].w * xv.w;
                    }
                }
                // Rolling prefetch: quarter j of next item's weights
                #pragma unroll
                for (int it = 0; it < 2; it++) {
                    const float4* wrn = (const float4*)
                        (W1n + (size_t)(qn * 32 + rbase + it * 4) * H_DIM);
                    wv[it][j] = wrn[j * 8 + c];
                }
                if (j == 0) {
                    bias_nxt[0] = b1n[qn * 32 + rbase];
                    bias_nxt[1] = b1n[qn * 32 + rbase + 4];
                }
            }

            // Distributing butterfly: lane c ends with token c's full sum.
            #pragma unroll
            for (int it = 0; it < 2; it++) {
                float a0 = acc[it][0], a1 = acc[it][1], a2 = acc[it][2], a3 = acc[it][3];
                float a4 = acc[it][4], a5 = acc[it][5], a6 = acc[it][6], a7 = acc[it][7];
                {
                    float s0 = (c & 4) ? a0 : a4, s1 = (c & 4) ? a1 : a5;
                    float s2 = (c & 4) ? a2 : a6, s3 = (c & 4) ? a3 : a7;
                    float r0 = __shfl_xor_sync(0xffffffffu, s0, 4);
                    float r1 = __shfl_xor_sync(0xffffffffu, s1, 4);
                    float r2 = __shfl_xor_sync(0xffffffffu, s2, 4);
                    float r3 = __shfl_xor_sync(0xffffffffu, s3, 4);
                    a0 = ((c & 4) ? a4 : a0) + r0;
                    a1 = ((c & 4) ? a5 : a1) + r1;
                    a2 = ((c & 4) ? a6 : a2) + r2;
                    a3 = ((c & 4) ? a7 : a3) + r3;
                }
                {
                    float s0 = (c & 2) ? a0 : a2, s1 = (c & 2) ? a1 : a3;
                    float r0 = __shfl_xor_sync(0xffffffffu, s0, 2);
                    float r1 = __shfl_xor_sync(0xffffffffu, s1, 2);
                    a0 = ((c & 2) ? a2 : a0) + r0;
                    a1 = ((c & 2) ? a3 : a1) + r1;
                }
                {
                    float s0 = (c & 1) ? a0 : a1;
                    float r0 = __shfl_xor_sync(0xffffffffu, s0, 1);
                    a0 = ((c & 1) ? a1 : a0) + r0;
                }
                const int tok = c;
                float v = gelu_exact(a0 + bias[it]);
                if (tok < nt)
                    g_h[(size_t)stoks[tok] * H4_DIM + q * 32 + rbase + it * 4] = v;
            }
            bias[0] = bias_nxt[0];
            bias[1] = bias_nxt[1];
        }
    }
}

// ============================================================================
// Layer 2: grid = N_NODES*NC. CTA (n, tc) processes ALL 8 row-items (16 rows
// each). 128 thr / 4 warps. Warp w owns 4 sequential rows q*16 + w*4 + it.
// Full 32-lane k-split [j*32+lane]; 1 LDS.128 -> 16 FFMA. Tokens in 2 halves.
// Rolling quarter prefetch during half h2=1.
// ============================================================================
__global__ __launch_bounds__(128, 4)
void layer2_kernel(const float* __restrict__ W2,
                   const float* __restrict__ b2,
                   float* __restrict__ out) {
    __shared__ float hs[TB][H4_DIM];   // 16 KB
    __shared__ int   stoks[TB];

    const int bid = blockIdx.x;
    const int tc  = bid & (NC - 1);
    const int n   = bid >> 2;
    const int base0 = tc * TB;

    const int tid = threadIdx.x;

    int spec_tok = 0;
    if (tid < TB) spec_tok = g_tokens[n * T_TOK + base0 + tid];
    const int nt_total = g_count[n];
    if (base0 >= nt_total) return;

    const int w    = tid >> 5;
    const int lane = tid & 31;
    const int rbase = w * 4;      // row within item = rbase + it

    const float* W2n = W2 + (size_t)n * H_DIM * H4_DIM;
    const float* b2n = b2 + n * H_DIM;

    // Initial weights + biases for item 0
    float4 wv[4][4];
    float  bias[4];
    #pragma unroll
    for (int it = 0; it < 4; it++) {
        const float4* wr = (const float4*)(W2n + (size_t)(rbase + it) * H4_DIM);
        #pragma unroll
        for (int j = 0; j < 4; j++) wv[it][j] = wr[j * 32 + lane];
        bias[it] = b2n[rbase + it];
    }

    for (int base = base0; base < nt_total; base += NC * TB) {
        const int nt = min(TB, nt_total - base);

        __syncthreads();
        if (tid < nt)
            stoks[tid] = (base == base0) ? spec_tok
                                         : g_tokens[n * T_TOK + base + tid];
        __syncthreads();
        // Stage h rows once for all 8 items: nt*128 float4; 128 thr x 8
        #pragma unroll
        for (int k = 0; k < 8; k++) {
            int idx = tid + k * 128;
            int tk = idx >> 7;
            int l4 = idx & 127;
            if (tk < nt)
                ((float4*)hs[tk])[l4] =
                    ((const float4*)(g_h + (size_t)stoks[tk] * H4_DIM))[l4];
        }
        __syncthreads();

        #pragma unroll 1
        for (int q = 0; q < 8; q++) {
            const int qn = (q + 1) & 7;
            float bias_nxt[4];

            #pragma unroll
            for (int h2 = 0; h2 < 2; h2++) {
                float acc[4][4];
                #pragma unroll
                for (int it = 0; it < 4; it++)
                    #pragma unroll
                    for (int tl = 0; tl < 4; tl++) acc[it][tl] = 0.f;

                #pragma unroll
                for (int j = 0; j < 4; j++) {
                    #pragma unroll
                    for (int tl = 0; tl < 4; tl++) {
                        const int t = h2 * 4 + tl;
                        if (t < nt) {
                            float4 hv = ((const float4*)hs[t])[j * 32 + lane];
                            #pragma unroll
                            for (int it = 0; it < 4; it++) {
                                acc[it][tl] += wv[it][j].x * hv.x + wv[it][j].y * hv.y
                                             + wv[it][j].z * hv.z + wv[it][j].w * hv.w;
                            }
                        }
                    }
                    // Rolling prefetch during second half (after last use of wv[*][j])
                    if (h2 == 1) {
                        #pragma unroll
                        for (int it = 0; it < 4; it++) {
                            const float4* wrn = (const float4*)
                                (W2n + (size_t)(qn * 16 + rbase + it) * H4_DIM);
                            wv[it][j] = wrn[j * 32 + lane];
                        }
                    }
                }
                if (h2 == 0) {
                    #pragma unroll
                    for (int it = 0; it < 4; it++)
                        bias_nxt[it] = b2n[qn * 16 + rbase + it];
                }

                // Distributing butterfly: token bits from lane {16,8}
                #pragma unroll
                for (int it = 0; it < 4; it++) {
                    float a0 = acc[it][0], a1 = acc[it][1];
                    float a2 = acc[it][2], a3 = acc[it][3];
                    {
                        float s0 = (lane & 16) ? a0 : a2, s1 = (lane & 16) ? a1 : a3;
                        float r0 = __shfl_xor_sync(0xffffffffu, s0, 16);
                        float r1 = __shfl_xor_sync(0xffffffffu, s1, 16);
                        a0 = ((lane & 16) ? a2 : a0) + r0;
                        a1 = ((lane & 16) ? a3 : a1) + r1;
                    }
                    {
                        float s0 = (lane & 8) ? a0 : a1;
                        float r0 = __shfl_xor_sync(0xffffffffu, s0, 8);
                        a0 = ((lane & 8) ? a1 : a0) + r0;
                    }
                    a0 += __shfl_xor_sync(0xffffffffu, a0, 4);
                    a0 += __shfl_xor_sync(0xffffffffu, a0, 2);
                    a0 += __shfl_xor_sync(0xffffffffu, a0, 1);

                    const int tok = h2 * 4 + (((lane & 16) ? 2 : 0) | ((lane & 8) ? 1 : 0));
                    if ((lane & 7) == 0 && tok < nt)
                        out[(size_t)stoks[tok] * H_DIM + q * 16 + rbase + it] = a0 + bias[it];
                }
            }
            #pragma unroll
            for (int it = 0; it < 4; it++) bias[it] = bias_nxt[it];
        }
    }
}

extern "C" void kernel_launch(void* const* d_in, const int* in_sizes, int n_in,
                              void* d_out, int out_size) {
    const float* x        = (const float*)d_in[0];
    const int*   node_ind = (const int*)  d_in[1];
    const float* W1       = (const float*)d_in[2];
    const float* b1       = (const float*)d_in[3];
    const float* W2       = (const float*)d_in[4];
    const float* b2       = (const float*)d_in[5];
    float*       out      = (float*)d_out;

    prep_kernel<<<1, 1024>>>(node_ind);
    layer1_kernel<<<N_NODES * NC, 128>>>(x, W1, b1);
    layer2_kernel<<<N_NODES * NC, 128>>>(W2, b2, out);
}

// round 16
// speedup vs baseline: 1.3564x; 1.3564x over previous
#include <cuda_runtime.h>
#include <math.h>

#define T_TOK   2048
#define H_DIM   128
#define H4_DIM  512
#define N_NODES 256
#define TB      8      // tokens per chunk
#define SLOTS   256    // queue slots per layer grid

// Scratch (allocation-free per harness rules)
__device__ int   g_tokens[N_NODES * T_TOK];
__device__ float g_h[T_TOK * H4_DIM];   // 4 MB intermediate (L2-resident)
__device__ int   g_nitems;
__device__ int   g_queue[1024];         // entry: (n<<20)|(nt<<16)|base

// Single-launch prep: counts + token lists + compact chunk queue.
__global__ void prep_kernel(const int* __restrict__ node_ind) {
    __shared__ int scnt[N_NODES];
    __shared__ int qpos;
    const int tid = threadIdx.x;
    if (tid < N_NODES) scnt[tid] = 0;
    if (tid == 0) qpos = 0;
    __syncthreads();
    #pragma unroll
    for (int t = tid; t < T_TOK; t += 1024) {
        int n = node_ind[t];
        int pos = atomicAdd(&scnt[n], 1);
        g_tokens[n * T_TOK + pos] = t;
    }
    __syncthreads();
    if (tid < N_NODES) {
        int cnt = scnt[tid];
        int nch = (cnt + TB - 1) >> 3;
        if (nch > 0) {
            int p = atomicAdd(&qpos, nch);
            for (int j = 0; j < nch; j++) {
                int base = j * TB;
                int nt = min(TB, cnt - base);
                g_queue[p + j] = (tid << 20) | (nt << 16) | base;
            }
        }
    }
    __syncthreads();
    if (tid == 0) g_nitems = qpos;
}

__device__ __forceinline__ float gelu_exact(float v) {
    return 0.5f * v * (1.0f + erff(v * 0.70710678118654752f));
}

// ============================================================================
// Layer 1: grid = SLOTS*8 = 2048. bid -> (slot, q rows-of-64). CTA loops over
// queue items slot, slot+256, ... (mostly exactly one). Per item: R12 body —
// 256 thr / 8 warps, warp w owns rows w*8+it*4+g, lane=(g<<3)|c, xs [j*8+c]
// broadcast loads (1 wavefront), xv shared across 2 rows, distributing
// butterfly (lane c -> token c, gelu once/lane). h staged in padded smem
// hbuf[8][72] then stored float4-coalesced.
// ============================================================================
__global__ __launch_bounds__(256, 3)
void layer1_kernel(const float* __restrict__ x,
                   const float* __restrict__ W1,
                   const float* __restrict__ b1) {
    __shared__ float xs[TB][H_DIM];     // 4 KB
    __shared__ float hbuf[TB][72];      // 2.25 KB, pad 72 (f4-aligned rows, 2-way ST conflict)
    __shared__ int   stoks[TB];

    const int bid  = blockIdx.x;
    const int slot = bid >> 3;
    const int q    = bid & 7;

    const int tid  = threadIdx.x;
    const int w    = tid >> 5;
    const int lane = tid & 31;
    const int g    = lane >> 3;   // row slot 0..3 (broadcast group)
    const int c    = lane & 7;    // k-chunk 0..7

    // nitems + first entry load issue in parallel (both always-valid addrs)
    const int e0 = g_queue[slot];
    const int nitems = g_nitems;

    for (int item = slot; item < nitems; item += SLOTS) {
        const int e    = (item == slot) ? e0 : g_queue[item];
        const int n    = e >> 20;
        const int nt   = (e >> 16) & 15;
        const int base = e & 0xFFFF;

        __syncthreads();   // protect smem reuse across items
        if (tid < nt) stoks[tid] = g_tokens[n * T_TOK + base + tid];
        __syncthreads();
        if (tid < nt * 32) {
            int tk = tid >> 5;
            int l4 = tid & 31;
            ((float4*)xs[tk])[l4] =
                ((const float4*)(x + (size_t)stoks[tk] * H_DIM))[l4];
        }
        __syncthreads();

        const float* W1c = W1 + (size_t)n * H4_DIM * H_DIM + (size_t)q * 64 * H_DIM;
        const float* b1c = b1 + n * H4_DIM + q * 64;

        float4 wv[2][4];
        float  bias[2];
        #pragma unroll
        for (int it = 0; it < 2; it++) {
            const int rr = w * 8 + it * 4 + g;
            const float4* wr = (const float4*)(W1c + (size_t)rr * H_DIM);
            #pragma unroll
            for (int j = 0; j < 4; j++) wv[it][j] = wr[j * 8 + c];
            bias[it] = b1c[rr];
        }

        float acc[2][TB];
        #pragma unroll
        for (int it = 0; it < 2; it++)
            #pragma unroll
            for (int t = 0; t < TB; t++) acc[it][t] = 0.f;

        #pragma unroll
        for (int t = 0; t < TB; t++) {
            if (t < nt) {
                #pragma unroll
                for (int j = 0; j < 4; j++) {
                    float4 xv = ((const float4*)xs[t])[j * 8 + c];
                    acc[0][t] += wv[0][j].x * xv.x + wv[0][j].y * xv.y
                               + wv[0][j].z * xv.z + wv[0][j].w * xv.w;
                    acc[1][t] += wv[1][j].x * xv.x + wv[1][j].y * xv.y
                               + wv[1][j].z * xv.z + wv[1][j].w * xv.w;
                }
            }
        }

        // Distributing butterfly: lane c ends with token c's full sum.
        #pragma unroll
        for (int it = 0; it < 2; it++) {
            float a0 = acc[it][0], a1 = acc[it][1], a2 = acc[it][2], a3 = acc[it][3];
            float a4 = acc[it][4], a5 = acc[it][5], a6 = acc[it][6], a7 = acc[it][7];
            {
                float s0 = (c & 4) ? a0 : a4, s1 = (c & 4) ? a1 : a5;
                float s2 = (c & 4) ? a2 : a6, s3 = (c & 4) ? a3 : a7;
                float r0 = __shfl_xor_sync(0xffffffffu, s0, 4);
                float r1 = __shfl_xor_sync(0xffffffffu, s1, 4);
                float r2 = __shfl_xor_sync(0xffffffffu, s2, 4);
                float r3 = __shfl_xor_sync(0xffffffffu, s3, 4);
                a0 = ((c & 4) ? a4 : a0) + r0;
                a1 = ((c & 4) ? a5 : a1) + r1;
                a2 = ((c & 4) ? a6 : a2) + r2;
                a3 = ((c & 4) ? a7 : a3) + r3;
            }
            {
                float s0 = (c & 2) ? a0 : a2, s1 = (c & 2) ? a1 : a3;
                float r0 = __shfl_xor_sync(0xffffffffu, s0, 2);
                float r1 = __shfl_xor_sync(0xffffffffu, s1, 2);
                a0 = ((c & 2) ? a2 : a0) + r0;
                a1 = ((c & 2) ? a3 : a1) + r1;
            }
            {
                float s0 = (c & 1) ? a0 : a1;
                float r0 = __shfl_xor_sync(0xffffffffu, s0, 1);
                a0 = ((c & 1) ? a1 : a0) + r0;
            }
            const int rr = w * 8 + it * 4 + g;
            hbuf[c][rr] = gelu_exact(a0 + bias[it]);  // token c, row rr
        }
        __syncthreads();

        // Coalesced h store: 8 tok x 64 rows = 128 float4, threads 0..127
        if (tid < 128) {
            int t  = tid >> 4;
            int f4 = tid & 15;
            if (t < nt) {
                float4 v = make_float4(hbuf[t][f4 * 4 + 0], hbuf[t][f4 * 4 + 1],
                                       hbuf[t][f4 * 4 + 2], hbuf[t][f4 * 4 + 3]);
                ((float4*)(g_h + (size_t)stoks[t] * H4_DIM + q * 64))[f4] = v;
            }
        }
    }
}

// ============================================================================
// Layer 2: grid = SLOTS*4 = 1024. bid -> (slot, q rows-of-32). R12 body:
// 256 thr / 8 warps, warp w owns 4 sequential rows q*32+w*4+it, full 32-lane
// k-split [j*32+lane] (conflict-free), 1 LDS.128 -> 16 FFMA, tokens in 2
// halves (acc[4][4]), distributing butterfly via lane bits {16,8}.
// ============================================================================
__global__ __launch_bounds__(256, 2)
void layer2_kernel(const float* __restrict__ W2,
                   const float* __restrict__ b2,
                   float* __restrict__ out) {
    __shared__ float hs[TB][H4_DIM];   // 16 KB
    __shared__ int   stoks[TB];

    const int bid  = blockIdx.x;
    const int slot = bid >> 2;
    const int q    = bid & 3;

    const int tid  = threadIdx.x;
    const int w    = tid >> 5;
    const int lane = tid & 31;

    const int e0 = g_queue[slot];
    const int nitems = g_nitems;

    for (int item = slot; item < nitems; item += SLOTS) {
        const int e    = (item == slot) ? e0 : g_queue[item];
        const int n    = e >> 20;
        const int nt   = (e >> 16) & 15;
        const int base = e & 0xFFFF;

        __syncthreads();
        if (tid < nt) stoks[tid] = g_tokens[n * T_TOK + base + tid];
        __syncthreads();
        // Stage h rows: nt*128 float4; 256 threads -> up to 4 each
        #pragma unroll
        for (int k = 0; k < 4; k++) {
            int idx = tid + k * 256;
            int tk = idx >> 7;
            int l4 = idx & 127;
            if (tk < nt)
                ((float4*)hs[tk])[l4] =
                    ((const float4*)(g_h + (size_t)stoks[tk] * H4_DIM))[l4];
        }
        __syncthreads();

        const int row0 = q * 32 + w * 4;
        const float* W2c = W2 + (size_t)n * H_DIM * H4_DIM + (size_t)row0 * H4_DIM;

        float4 wv[4][4];
        float  bias[4];
        #pragma unroll
        for (int it = 0; it < 4; it++) {
            const float4* wr = (const float4*)(W2c + (size_t)it * H4_DIM);
            #pragma unroll
            for (int j = 0; j < 4; j++) wv[it][j] = wr[j * 32 + lane];
            bias[it] = b2[n * H_DIM + row0 + it];
        }

        #pragma unroll
        for (int h2 = 0; h2 < 2; h2++) {
            float acc[4][4];
            #pragma unroll
            for (int it = 0; it < 4; it++)
                #pragma unroll
                for (int tl = 0; tl < 4; tl++) acc[it][tl] = 0.f;

            #pragma unroll
            for (int tl = 0; tl < 4; tl++) {
                const int t = h2 * 4 + tl;
                if (t < nt) {
                    #pragma unroll
                    for (int j = 0; j < 4; j++) {
                        float4 hv = ((const float4*)hs[t])[j * 32 + lane]; // 1 load -> 4 rows
                        #pragma unroll
                        for (int it = 0; it < 4; it++) {
                            acc[it][tl] += wv[it][j].x * hv.x + wv[it][j].y * hv.y
                                         + wv[it][j].z * hv.z + wv[it][j].w * hv.w;
                        }
                    }
                }
            }

            // Distributing butterfly: token bit1 <- (lane&16), bit0 <- (lane&8)
            #pragma unroll
            for (int it = 0; it < 4; it++) {
                float a0 = acc[it][0], a1 = acc[it][1];
                float a2 = acc[it][2], a3 = acc[it][3];
                {
                    float s0 = (lane & 16) ? a0 : a2, s1 = (lane & 16) ? a1 : a3;
                    float r0 = __shfl_xor_sync(0xffffffffu, s0, 16);
                    float r1 = __shfl_xor_sync(0xffffffffu, s1, 16);
                    a0 = ((lane & 16) ? a2 : a0) + r0;
                    a1 = ((lane & 16) ? a3 : a1) + r1;
                }
                {
                    float s0 = (lane & 8) ? a0 : a1;
                    float r0 = __shfl_xor_sync(0xffffffffu, s0, 8);
                    a0 = ((lane & 8) ? a1 : a0) + r0;
                }
                a0 += __shfl_xor_sync(0xffffffffu, a0, 4);
                a0 += __shfl_xor_sync(0xffffffffu, a0, 2);
                a0 += __shfl_xor_sync(0xffffffffu, a0, 1);

                const int tok = h2 * 4 + (((lane & 16) ? 2 : 0) | ((lane & 8) ? 1 : 0));
                if ((lane & 7) == 0 && tok < nt)
                    out[(size_t)stoks[tok] * H_DIM + row0 + it] = a0 + bias[it];
            }
        }
    }
}

extern "C" void kernel_launch(void* const* d_in, const int* in_sizes, int n_in,
                              void* d_out, int out_size) {
    const float* x        = (const float*)d_in[0];
    const int*   node_ind = (const int*)  d_in[1];
    const float* W1       = (const float*)d_in[2];
    const float* b1       = (const float*)d_in[3];
    const float* W2       = (const float*)d_in[4];
    const float* b2       = (const float*)d_in[5];
    float*       out      = (float*)d_out;

    prep_kernel<<<1, 1024>>>(node_ind);
    layer1_kernel<<<SLOTS * 8, 256>>>(x, W1, b1);
    layer2_kernel<<<SLOTS * 4, 256>>>(W2, b2, out);
}

// round 17
// speedup vs baseline: 1.4066x; 1.0370x over previous
#include <cuda_runtime.h>
#include <math.h>

#define T_TOK   2048
#define H_DIM   128
#define H4_DIM  512
#define N_NODES 256
#define TB      8      // tokens per chunk
#define SLOTS   256    // queue slots per layer grid

// Scratch (allocation-free per harness rules)
__device__ int   g_tokens[N_NODES * T_TOK];
__device__ float g_h[T_TOK * H4_DIM];   // 4 MB intermediate (L2-resident)
__device__ int   g_nitems;
__device__ int   g_queue[1024];         // entry: (n<<20)|(nt<<16)|base

// Single-launch prep: counts + token lists + compact chunk queue.
__global__ void prep_kernel(const int* __restrict__ node_ind) {
    __shared__ int scnt[N_NODES];
    __shared__ int qpos;
    const int tid = threadIdx.x;
    if (tid < N_NODES) scnt[tid] = 0;
    if (tid == 0) qpos = 0;
    __syncthreads();
    #pragma unroll
    for (int t = tid; t < T_TOK; t += 1024) {
        int n = node_ind[t];
        int pos = atomicAdd(&scnt[n], 1);
        g_tokens[n * T_TOK + pos] = t;
    }
    __syncthreads();
    if (tid < N_NODES) {
        int cnt = scnt[tid];
        int nch = (cnt + TB - 1) >> 3;
        if (nch > 0) {
            int p = atomicAdd(&qpos, nch);
            for (int j = 0; j < nch; j++) {
                int base = j * TB;
                int nt = min(TB, cnt - base);
                g_queue[p + j] = (tid << 20) | (nt << 16) | base;
            }
        }
    }
    __syncthreads();
    if (tid == 0) g_nitems = qpos;
}

__device__ __forceinline__ float gelu_exact(float v) {
    return 0.5f * v * (1.0f + erff(v * 0.70710678118654752f));
}

// ============================================================================
// Layer 1: grid = SLOTS*8 = 2048. bid -> (slot, q rows-of-64).
// Latency-chain surgery vs R16: weight/bias LDGs issue right after entry
// decode (overlap staging); x gather reads g_tokens directly (kills one
// bar + smem round trip). Compute body identical to R16/R12.
// ============================================================================
__global__ __launch_bounds__(256, 3)
void layer1_kernel(const float* __restrict__ x,
                   const float* __restrict__ W1,
                   const float* __restrict__ b1) {
    __shared__ float xs[TB][H_DIM];     // 4 KB
    __shared__ float hbuf[TB][72];      // 2.25 KB padded
    __shared__ int   stoks[TB];

    const int bid  = blockIdx.x;
    const int slot = bid >> 3;
    const int q    = bid & 7;

    const int tid  = threadIdx.x;
    const int w    = tid >> 5;
    const int lane = tid & 31;
    const int g    = lane >> 3;   // row slot 0..3 (broadcast group)
    const int c    = lane & 7;    // k-chunk 0..7

    const int e0 = g_queue[slot];
    const int nitems = g_nitems;

    for (int item = slot; item < nitems; item += SLOTS) {
        const int e    = (item == slot) ? e0 : g_queue[item];
        const int n    = e >> 20;
        const int nt   = (e >> 16) & 15;
        const int base = e & 0xFFFF;

        // ---- Weight/bias loads FIRST (depend only on n) ----
        const float* W1c = W1 + (size_t)n * H4_DIM * H_DIM + (size_t)q * 64 * H_DIM;
        const float* b1c = b1 + n * H4_DIM + q * 64;
        float4 wv[2][4];
        float  bias[2];
        #pragma unroll
        for (int it = 0; it < 2; it++) {
            const int rr = w * 8 + it * 4 + g;
            const float4* wr = (const float4*)(W1c + (size_t)rr * H_DIM);
            #pragma unroll
            for (int j = 0; j < 4; j++) wv[it][j] = wr[j * 8 + c];
            bias[it] = b1c[rr];
        }

        __syncthreads();   // protect smem reuse across items
        // Token ids for the later h store (parallel, not on gather's path)
        if (tid < nt) stoks[tid] = g_tokens[n * T_TOK + base + tid];
        // x gather: token id read directly (same addr per 32-thread group -> 1 sector)
        {
            int tk = tid >> 5;
            if (tk < nt) {
                int tok = g_tokens[n * T_TOK + base + tk];
                ((float4*)xs[tk])[lane] =
                    ((const float4*)(x + (size_t)tok * H_DIM))[lane];
            }
        }
        __syncthreads();

        float acc[2][TB];
        #pragma unroll
        for (int it = 0; it < 2; it++)
            #pragma unroll
            for (int t = 0; t < TB; t++) acc[it][t] = 0.f;

        #pragma unroll
        for (int t = 0; t < TB; t++) {
            if (t < nt) {
                #pragma unroll
                for (int j = 0; j < 4; j++) {
                    float4 xv = ((const float4*)xs[t])[j * 8 + c];
                    acc[0][t] += wv[0][j].x * xv.x + wv[0][j].y * xv.y
                               + wv[0][j].z * xv.z + wv[0][j].w * xv.w;
                    acc[1][t] += wv[1][j].x * xv.x + wv[1][j].y * xv.y
                               + wv[1][j].z * xv.z + wv[1][j].w * xv.w;
                }
            }
        }

        // Distributing butterfly: lane c ends with token c's full sum.
        #pragma unroll
        for (int it = 0; it < 2; it++) {
            float a0 = acc[it][0], a1 = acc[it][1], a2 = acc[it][2], a3 = acc[it][3];
            float a4 = acc[it][4], a5 = acc[it][5], a6 = acc[it][6], a7 = acc[it][7];
            {
                float s0 = (c & 4) ? a0 : a4, s1 = (c & 4) ? a1 : a5;
                float s2 = (c & 4) ? a2 : a6, s3 = (c & 4) ? a3 : a7;
                float r0 = __shfl_xor_sync(0xffffffffu, s0, 4);
                float r1 = __shfl_xor_sync(0xffffffffu, s1, 4);
                float r2 = __shfl_xor_sync(0xffffffffu, s2, 4);
                float r3 = __shfl_xor_sync(0xffffffffu, s3, 4);
                a0 = ((c & 4) ? a4 : a0) + r0;
                a1 = ((c & 4) ? a5 : a1) + r1;
                a2 = ((c & 4) ? a6 : a2) + r2;
                a3 = ((c & 4) ? a7 : a3) + r3;
            }
            {
                float s0 = (c & 2) ? a0 : a2, s1 = (c & 2) ? a1 : a3;
                float r0 = __shfl_xor_sync(0xffffffffu, s0, 2);
                float r1 = __shfl_xor_sync(0xffffffffu, s1, 2);
                a0 = ((c & 2) ? a2 : a0) + r0;
                a1 = ((c & 2) ? a3 : a1) + r1;
            }
            {
                float s0 = (c & 1) ? a0 : a1;
                float r0 = __shfl_xor_sync(0xffffffffu, s0, 1);
                a0 = ((c & 1) ? a1 : a0) + r0;
            }
            const int rr = w * 8 + it * 4 + g;
            hbuf[c][rr] = gelu_exact(a0 + bias[it]);  // token c, row rr
        }
        __syncthreads();

        // Coalesced h store: 8 tok x 64 rows = 128 float4, threads 0..127
        if (tid < 128) {
            int t  = tid >> 4;
            int f4 = tid & 15;
            if (t < nt) {
                float4 v = make_float4(hbuf[t][f4 * 4 + 0], hbuf[t][f4 * 4 + 1],
                                       hbuf[t][f4 * 4 + 2], hbuf[t][f4 * 4 + 3]);
                ((float4*)(g_h + (size_t)stoks[t] * H4_DIM + q * 64))[f4] = v;
            }
        }
    }
}

// ============================================================================
// Layer 2: grid = SLOTS*4 = 1024. bid -> (slot, q rows-of-32).
// Weights hoisted before h staging; h gather reads g_tokens directly
// (same addr per 128-thread group -> 1 sector). Compute body = R16/R12.
// ============================================================================
__global__ __launch_bounds__(256, 2)
void layer2_kernel(const float* __restrict__ W2,
                   const float* __restrict__ b2,
                   float* __restrict__ out) {
    __shared__ float hs[TB][H4_DIM];   // 16 KB
    __shared__ int   stoks[TB];

    const int bid  = blockIdx.x;
    const int slot = bid >> 2;
    const int q    = bid & 3;

    const int tid  = threadIdx.x;
    const int w    = tid >> 5;
    const int lane = tid & 31;

    const int e0 = g_queue[slot];
    const int nitems = g_nitems;

    for (int item = slot; item < nitems; item += SLOTS) {
        const int e    = (item == slot) ? e0 : g_queue[item];
        const int n    = e >> 20;
        const int nt   = (e >> 16) & 15;
        const int base = e & 0xFFFF;

        // ---- Weight/bias loads FIRST (depend only on n) ----
        const int row0 = q * 32 + w * 4;
        const float* W2c = W2 + (size_t)n * H_DIM * H4_DIM + (size_t)row0 * H4_DIM;
        float4 wv[4][4];
        float  bias[4];
        #pragma unroll
        for (int it = 0; it < 4; it++) {
            const float4* wr = (const float4*)(W2c + (size_t)it * H4_DIM);
            #pragma unroll
            for (int j = 0; j < 4; j++) wv[it][j] = wr[j * 32 + lane];
            bias[it] = b2[n * H_DIM + row0 + it];
        }

        __syncthreads();
        if (tid < nt) stoks[tid] = g_tokens[n * T_TOK + base + tid];
        // h gather: token id read directly per 128-thread group
        #pragma unroll
        for (int k = 0; k < 4; k++) {
            int idx = tid + k * 256;
            int tk = idx >> 7;
            int l4 = idx & 127;
            if (tk < nt) {
                int tok = g_tokens[n * T_TOK + base + tk];
                ((float4*)hs[tk])[l4] =
                    ((const float4*)(g_h + (size_t)tok * H4_DIM))[l4];
            }
        }
        __syncthreads();

        #pragma unroll
        for (int h2 = 0; h2 < 2; h2++) {
            float acc[4][4];
            #pragma unroll
            for (int it = 0; it < 4; it++)
                #pragma unroll
                for (int tl = 0; tl < 4; tl++) acc[it][tl] = 0.f;

            #pragma unroll
            for (int tl = 0; tl < 4; tl++) {
                const int t = h2 * 4 + tl;
                if (t < nt) {
                    #pragma unroll
                    for (int j = 0; j < 4; j++) {
                        float4 hv = ((const float4*)hs[t])[j * 32 + lane]; // 1 load -> 4 rows
                        #pragma unroll
                        for (int it = 0; it < 4; it++) {
                            acc[it][tl] += wv[it][j].x * hv.x + wv[it][j].y * hv.y
                                         + wv[it][j].z * hv.z + wv[it][j].w * hv.w;
                        }
                    }
                }
            }

            // Distributing butterfly: token bit1 <- (lane&16), bit0 <- (lane&8)
            #pragma unroll
            for (int it = 0; it < 4; it++) {
                float a0 = acc[it][0], a1 = acc[it][1];
                float a2 = acc[it][2], a3 = acc[it][3];
                {
                    float s0 = (lane & 16) ? a0 : a2, s1 = (lane & 16) ? a1 : a3;
                    float r0 = __shfl_xor_sync(0xffffffffu, s0, 16);
                    float r1 = __shfl_xor_sync(0xffffffffu, s1, 16);
                    a0 = ((lane & 16) ? a2 : a0) + r0;
                    a1 = ((lane & 16) ? a3 : a1) + r1;
                }
                {
                    float s0 = (lane & 8) ? a0 : a1;
                    float r0 = __shfl_xor_sync(0xffffffffu, s0, 8);
                    a0 = ((lane & 8) ? a1 : a0) + r0;
                }
                a0 += __shfl_xor_sync(0xffffffffu, a0, 4);
                a0 += __shfl_xor_sync(0xffffffffu, a0, 2);
                a0 += __shfl_xor_sync(0xffffffffu, a0, 1);

                const int tok = h2 * 4 + (((lane & 16) ? 2 : 0) | ((lane & 8) ? 1 : 0));
                if ((lane & 7) == 0 && tok < nt)
                    out[(size_t)stoks[tok] * H_DIM + row0 + it] = a0 + bias[it];
            }
        }
    }
}

extern "C" void kernel_launch(void* const* d_in, const int* in_sizes, int n_in,
                              void* d_out, int out_size) {
    const float* x        = (const float*)d_in[0];
    const int*   node_ind = (const int*)  d_in[1];
    const float* W1       = (const float*)d_in[2];
    const float* b1       = (const float*)d_in[3];
    const float* W2       = (const float*)d_in[4];
    const float* b2       = (const float*)d_in[5];
    float*       out      = (float*)d_out;

    prep_kernel<<<1, 1024>>>(node_ind);
    layer1_kernel<<<SLOTS * 8, 256>>>(x, W1, b1);
    layer2_kernel<<<SLOTS * 4, 256>>>(W2, b2, out);
}